// round 3
// baseline (speedup 1.0000x reference)
#include <cuda_runtime.h>
#include <cstdint>

#define D_MODEL 1024
#define N_HEADS 16
#define D_HEAD  64
#define D_FF    4096
#define BATCH   4
#define SEQ     1024
#define M_TOK   (BATCH*SEQ)   // 4096

// ---------------- scratch (allocation-free: device globals) ----------------
__device__ float g_h  [M_TOK*D_MODEL];
__device__ float g_q  [M_TOK*D_MODEL];
__device__ float g_k  [M_TOK*D_MODEL];
__device__ float g_v  [M_TOK*D_MODEL];
__device__ float g_vT [M_TOK*D_MODEL];
__device__ float g_o1 [M_TOK*D_MODEL];
__device__ float g_h2 [M_TOK*D_MODEL];
__device__ float g_ff [M_TOK*D_FF];

// ---------------- helpers ----------------
__device__ __forceinline__ uint32_t f2tf(float f) {
    uint32_t u;
    asm("cvt.rna.tf32.f32 %0, %1;" : "=r"(u) : "f"(f));
    return u;
}

__device__ __forceinline__ void mma_tf32(float* c, uint32_t a0, uint32_t a1, uint32_t a2, uint32_t a3,
                                         uint32_t b0, uint32_t b1) {
    asm volatile(
        "mma.sync.aligned.m16n8k8.row.col.f32.tf32.tf32.f32 "
        "{%0,%1,%2,%3}, {%4,%5,%6,%7}, {%8,%9}, {%0,%1,%2,%3};\n"
        : "+f"(c[0]), "+f"(c[1]), "+f"(c[2]), "+f"(c[3])
        : "r"(a0), "r"(a1), "r"(a2), "r"(a3), "r"(b0), "r"(b1));
}

// ---------------- LayerNorm (unbiased var, /(std+eps)) ----------------
__global__ void ln_kernel(const float* __restrict__ x, const float* __restrict__ g,
                          const float* __restrict__ b, float* __restrict__ out) {
    int row = blockIdx.x;
    int t = threadIdx.x;  // 256 threads, 4 floats each
    const float4* xr = (const float4*)(x + (size_t)row * D_MODEL);
    float4 v = xr[t];
    __shared__ float red[8];

    float s = v.x + v.y + v.z + v.w;
    #pragma unroll
    for (int o = 16; o; o >>= 1) s += __shfl_xor_sync(0xffffffffu, s, o);
    if ((t & 31) == 0) red[t >> 5] = s;
    __syncthreads();
    float tot = red[0]+red[1]+red[2]+red[3]+red[4]+red[5]+red[6]+red[7];
    float mean = tot * (1.0f / D_MODEL);

    float dx = v.x - mean, dy = v.y - mean, dz = v.z - mean, dw = v.w - mean;
    float ss = dx*dx + dy*dy + dz*dz + dw*dw;
    #pragma unroll
    for (int o = 16; o; o >>= 1) ss += __shfl_xor_sync(0xffffffffu, ss, o);
    __syncthreads();
    if ((t & 31) == 0) red[t >> 5] = ss;
    __syncthreads();
    float vtot = red[0]+red[1]+red[2]+red[3]+red[4]+red[5]+red[6]+red[7];
    float inv = 1.0f / (sqrtf(vtot * (1.0f / (D_MODEL - 1))) + 1e-12f);

    float4 g4 = ((const float4*)g)[t];
    float4 b4 = ((const float4*)b)[t];
    float4 o4;
    o4.x = g4.x * dx * inv + b4.x;
    o4.y = g4.y * dy * inv + b4.y;
    o4.z = g4.z * dz * inv + b4.z;
    o4.w = g4.w * dw * inv + b4.w;
    ((float4*)(out + (size_t)row * D_MODEL))[t] = o4;
}

// ---------------- softmax (in-place over rows of length SEQ) ----------------
__global__ void softmax_kernel(float* __restrict__ attn) {
    size_t row = blockIdx.x;
    float4* p = (float4*)(attn + row * SEQ);
    int t = threadIdx.x;
    float4 v = p[t];
    __shared__ float red[8];

    float mx = fmaxf(fmaxf(v.x, v.y), fmaxf(v.z, v.w));
    #pragma unroll
    for (int o = 16; o; o >>= 1) mx = fmaxf(mx, __shfl_xor_sync(0xffffffffu, mx, o));
    if ((t & 31) == 0) red[t >> 5] = mx;
    __syncthreads();
    mx = fmaxf(fmaxf(fmaxf(red[0],red[1]),fmaxf(red[2],red[3])),
               fmaxf(fmaxf(red[4],red[5]),fmaxf(red[6],red[7])));

    v.x = expf(v.x - mx); v.y = expf(v.y - mx);
    v.z = expf(v.z - mx); v.w = expf(v.w - mx);
    float s = v.x + v.y + v.z + v.w;
    #pragma unroll
    for (int o = 16; o; o >>= 1) s += __shfl_xor_sync(0xffffffffu, s, o);
    __syncthreads();
    if ((t & 31) == 0) red[t >> 5] = s;
    __syncthreads();
    float tot = red[0]+red[1]+red[2]+red[3]+red[4]+red[5]+red[6]+red[7];
    float inv = 1.0f / tot;
    v.x *= inv; v.y *= inv; v.z *= inv; v.w *= inv;
    p[t] = v;
}

// ---------------- V transpose: v[b,s,h,d] -> vT[(b*H+h)*64+d][s] ----------------
__global__ void transpose_v(const float* __restrict__ v, float* __restrict__ vT) {
    __shared__ float tile[32][33];
    int bh = blockIdx.z;             // b*H + h
    int b = bh / N_HEADS, h = bh % N_HEADS;
    int s0 = blockIdx.x * 32;
    int d0 = blockIdx.y * 32;
    int tx = threadIdx.x, ty = threadIdx.y;  // 32 x 8
    const float* src = v + ((size_t)b * SEQ) * D_MODEL + h * D_HEAD;
    #pragma unroll
    for (int i = 0; i < 32; i += 8)
        tile[ty + i][tx] = src[(size_t)(s0 + ty + i) * D_MODEL + d0 + tx];
    __syncthreads();
    float* dst = vT + ((size_t)bh * D_HEAD) * SEQ;
    #pragma unroll
    for (int i = 0; i < 32; i += 8)
        dst[(size_t)(d0 + ty + i) * SEQ + s0 + tx] = tile[tx][ty + i];
}

// ---------------- generalized tf32 GEMM: C = scale*(A[M,K] @ B[N,K]^T) (+bias)(+res)(relu)
//
// Shared-memory layout (per row of 16 k-values, stride 16 words):
//   logical chunk t (t = 0..3) holds k in {t, t+4, t+8, t+12} at sub-index i = k>>2.
//   physical chunk = t ^ ((row>>1) & 3)   (XOR swizzle)
// Properties (verified): all compute-side fragment loads are single LDS.128,
// conflict-free; the 4x STS.32 on the store side hit 32 distinct banks.
// A thread's LDS.128 of chunk t at row r yields exactly its mma operands for
// both kk-steps: [k=t, k=t+4, k=t+8, k=t+12] = {a0/a2 kk0, a0/a2 kk1} etc.
#define BM 128
#define BN 128
#define BK 16
#define KSW 16  // smem row stride in words

__global__ void __launch_bounds__(256, 2)
gemm_tf32(const float* __restrict__ A, const float* __restrict__ B,
          float* __restrict__ C, const float* __restrict__ bias,
          const float* __restrict__ res,
          int M, int N, int K, int lda, int ldb, int ldc,
          float scale, int relu, int zmod,
          long long aLo, long long aHi, long long bLo, long long bHi,
          long long cLo, long long cHi)
{
    int z = blockIdx.z;
    int zlo = z % zmod, zhi = z / zmod;
    A += (size_t)zlo * aLo + (size_t)zhi * aHi;
    B += (size_t)zlo * bLo + (size_t)zhi * bHi;
    size_t coff = (size_t)zlo * cLo + (size_t)zhi * cHi;
    C += coff;
    if (res) res += coff;

    __shared__ uint32_t As[2][BM * KSW];
    __shared__ uint32_t Bs[2][BN * KSW];

    int tid = threadIdx.x;
    int lane = tid & 31;
    int warp = tid >> 5;
    int wm = (warp & 3) * 32;   // warp m offset (4 warps in M)
    int wn = (warp >> 2) * 64;  // warp n offset (2 warps in N)

    int m0 = blockIdx.y * BM;
    int n0 = blockIdx.x * BN;

    int lr = tid >> 2;          // 0..63 (row within tile for global staging)
    int c4 = tid & 3;           // sub-index i of this thread's 4 staged values
    int lc = c4 * 4;            // k offset of the float4 global load

    float acc[2][8][4];
    #pragma unroll
    for (int i = 0; i < 2; i++)
        #pragma unroll
        for (int j = 0; j < 8; j++)
            #pragma unroll
            for (int c = 0; c < 4; c++) acc[i][j][c] = 0.f;

    float4 aReg[2], bReg[2];

    auto loadg = [&](int t) {
        int k0 = t * BK;
        #pragma unroll
        for (int i = 0; i < 2; i++) {
            int r = lr + i * 64;
            int gm = m0 + r;
            if (gm < M) aReg[i] = *(const float4*)(A + (size_t)gm * lda + k0 + lc);
            else        aReg[i] = make_float4(0.f, 0.f, 0.f, 0.f);
            int gn = n0 + r;
            if (gn < N) bReg[i] = *(const float4*)(B + (size_t)gn * ldb + k0 + lc);
            else        bReg[i] = make_float4(0.f, 0.f, 0.f, 0.f);
        }
    };
    // swizzled scalar stores: value j (k = lc+j, logical chunk t=j, sub i=c4)
    auto stores = [&](int buf) {
        #pragma unroll
        for (int i = 0; i < 2; i++) {
            int r = lr + i * 64;
            int sw = (r >> 1) & 3;
            uint32_t* pa = &As[buf][r * KSW + c4];
            float av[4] = {aReg[i].x, aReg[i].y, aReg[i].z, aReg[i].w};
            #pragma unroll
            for (int j = 0; j < 4; j++) pa[((j ^ sw) << 2)] = f2tf(av[j]);
            uint32_t* pb = &Bs[buf][r * KSW + c4];
            float bv[4] = {bReg[i].x, bReg[i].y, bReg[i].z, bReg[i].w};
            #pragma unroll
            for (int j = 0; j < 4; j++) pb[((j ^ sw) << 2)] = f2tf(bv[j]);
        }
    };
    auto compute = [&](int buf) {
        int t = lane & 3;
        int rl = lane >> 2;
        // A fragments: 2 mt x 2 rows, one LDS.128 each (covers both kk steps)
        uint4 afr[2][2];
        #pragma unroll
        for (int mt = 0; mt < 2; ++mt) {
            #pragma unroll
            for (int h = 0; h < 2; ++h) {
                int row = wm + mt * 16 + h * 8 + rl;
                int chunk = t ^ ((row >> 1) & 3);
                afr[mt][h] = *(const uint4*)&As[buf][row * KSW + (chunk << 2)];
            }
        }
        // B fragments + MMAs, nt-streamed
        #pragma unroll
        for (int nt = 0; nt < 8; ++nt) {
            int row = wn + nt * 8 + rl;
            int chunk = t ^ ((row >> 1) & 3);
            uint4 bfr = *(const uint4*)&Bs[buf][row * KSW + (chunk << 2)];
            #pragma unroll
            for (int mt = 0; mt < 2; ++mt) {
                // kk = 0: k in [0,8)
                mma_tf32(acc[mt][nt], afr[mt][0].x, afr[mt][1].x, afr[mt][0].y, afr[mt][1].y,
                         bfr.x, bfr.y);
                // kk = 1: k in [8,16)
                mma_tf32(acc[mt][nt], afr[mt][0].z, afr[mt][1].z, afr[mt][0].w, afr[mt][1].w,
                         bfr.z, bfr.w);
            }
        }
    };

    int nk = K / BK;
    loadg(0); stores(0); __syncthreads();
    int buf = 0;
    for (int t = 0; t < nk; ++t) {
        if (t + 1 < nk) loadg(t + 1);
        compute(buf);
        if (t + 1 < nk) { stores(buf ^ 1); __syncthreads(); }
        buf ^= 1;
    }

    // epilogue (vectorized: float2 per (row, col-pair))
    #pragma unroll
    for (int mt = 0; mt < 2; ++mt) {
        #pragma unroll
        for (int nt = 0; nt < 8; ++nt) {
            int rbase = m0 + wm + mt * 16 + (lane >> 2);
            int cbase = n0 + wn + nt * 8 + (lane & 3) * 2;
            #pragma unroll
            for (int h = 0; h < 2; ++h) {
                int rr = rbase + h * 8;
                if (rr < M && cbase + 1 < N) {
                    float v0 = acc[mt][nt][h * 2 + 0] * scale;
                    float v1 = acc[mt][nt][h * 2 + 1] * scale;
                    if (bias) { float2 bb = *(const float2*)(bias + cbase); v0 += bb.x; v1 += bb.y; }
                    if (res)  { float2 rr2 = *(const float2*)(res + (size_t)rr * ldc + cbase); v0 += rr2.x; v1 += rr2.y; }
                    if (relu) { v0 = fmaxf(v0, 0.f); v1 = fmaxf(v1, 0.f); }
                    *(float2*)(C + (size_t)rr * ldc + cbase) = make_float2(v0, v1);
                } else if (rr < M) {
                    #pragma unroll
                    for (int c = 0; c < 2; ++c) {
                        int cc = cbase + c;
                        if (cc < N) {
                            float val = acc[mt][nt][h * 2 + c] * scale;
                            if (bias) val += bias[cc];
                            if (res)  val += res[(size_t)rr * ldc + cc];
                            if (relu) val = fmaxf(val, 0.f);
                            C[(size_t)rr * ldc + cc] = val;
                        }
                    }
                }
            }
        }
    }
}

// ---------------- launch ----------------
extern "C" void kernel_launch(void* const* d_in, const int* in_sizes, int n_in,
                              void* d_out, int out_size) {
    const float* x     = (const float*)d_in[0];
    const float* ln1_g = (const float*)d_in[1];
    const float* ln1_b = (const float*)d_in[2];
    const float* wq    = (const float*)d_in[3];
    const float* bq    = (const float*)d_in[4];
    const float* wk    = (const float*)d_in[5];
    const float* bk    = (const float*)d_in[6];
    const float* wv    = (const float*)d_in[7];
    const float* bv    = (const float*)d_in[8];
    const float* ln2_g = (const float*)d_in[9];
    const float* ln2_b = (const float*)d_in[10];
    const float* w1    = (const float*)d_in[11];
    const float* b1    = (const float*)d_in[12];
    const float* w2    = (const float*)d_in[13];
    const float* b2    = (const float*)d_in[14];

    float* out  = (float*)d_out;
    float* attn = out + (size_t)BATCH * SEQ * D_MODEL;

    float *h, *q, *k, *v, *vT, *o1, *h2, *ff;
    cudaGetSymbolAddress((void**)&h,  g_h);
    cudaGetSymbolAddress((void**)&q,  g_q);
    cudaGetSymbolAddress((void**)&k,  g_k);
    cudaGetSymbolAddress((void**)&v,  g_v);
    cudaGetSymbolAddress((void**)&vT, g_vT);
    cudaGetSymbolAddress((void**)&o1, g_o1);
    cudaGetSymbolAddress((void**)&h2, g_h2);
    cudaGetSymbolAddress((void**)&ff, g_ff);

    dim3 blk(256);

    // 1) LN1
    ln_kernel<<<M_TOK, 256>>>(x, ln1_g, ln1_b, h);

    // 2) Q, K, V projections: [4096,1024] x [1024,1024]^T
    gemm_tf32<<<dim3(8, 32, 1), blk>>>(h, wq, q, bq, nullptr,
        M_TOK, D_MODEL, D_MODEL, D_MODEL, D_MODEL, D_MODEL, 1.f, 0, 1, 0,0,0,0,0,0);
    gemm_tf32<<<dim3(8, 32, 1), blk>>>(h, wk, k, bk, nullptr,
        M_TOK, D_MODEL, D_MODEL, D_MODEL, D_MODEL, D_MODEL, 1.f, 0, 1, 0,0,0,0,0,0);
    gemm_tf32<<<dim3(8, 32, 1), blk>>>(h, wv, v, bv, nullptr,
        M_TOK, D_MODEL, D_MODEL, D_MODEL, D_MODEL, D_MODEL, 1.f, 0, 1, 0,0,0,0,0,0);

    // 3) V transpose for ctx GEMM (B operand must be [n][k] = [d][s])
    transpose_v<<<dim3(32, 2, BATCH * N_HEADS), dim3(32, 8)>>>(v, vT);

    // 4) scores = q @ k^T / 8, batched over z = h*B + b, written straight to attn output
    gemm_tf32<<<dim3(8, 8, N_HEADS * BATCH), blk>>>(q, k, attn, nullptr, nullptr,
        SEQ, SEQ, D_HEAD, D_MODEL, D_MODEL, SEQ, 0.125f, 0, BATCH,
        (long long)SEQ * D_MODEL, 64,
        (long long)SEQ * D_MODEL, 64,
        (long long)SEQ * SEQ, (long long)BATCH * SEQ * SEQ);

    // 5) softmax in place (rows of attn)
    softmax_kernel<<<N_HEADS * BATCH * SEQ, 256>>>(attn);

    // 6) ctx = attn @ v  (+ residual x), batched over z = h*B + b
    gemm_tf32<<<dim3(1, 8, N_HEADS * BATCH), blk>>>(attn, vT, o1, nullptr, x,
        SEQ, D_HEAD, SEQ, SEQ, SEQ, D_MODEL, 1.f, 0, BATCH,
        (long long)SEQ * SEQ, (long long)BATCH * SEQ * SEQ,
        (long long)N_HEADS * D_HEAD * SEQ, (long long)D_HEAD * SEQ,
        (long long)SEQ * D_MODEL, 64);

    // 7) LN2
    ln_kernel<<<M_TOK, 256>>>(o1, ln2_g, ln2_b, h2);

    // 8) FFN1: relu(h2 @ w1^T + b1)
    gemm_tf32<<<dim3(32, 32, 1), blk>>>(h2, w1, ff, b1, nullptr,
        M_TOK, D_FF, D_MODEL, D_MODEL, D_MODEL, D_FF, 1.f, 1, 1, 0,0,0,0,0,0);

    // 9) FFN2: ff @ w2^T + b2 + o1  -> final out
    gemm_tf32<<<dim3(8, 32, 1), blk>>>(ff, w2, out, b2, o1,
        M_TOK, D_MODEL, D_FF, D_FF, D_FF, D_MODEL, 1.f, 0, 1, 0,0,0,0,0,0);
}

// round 4
// speedup vs baseline: 1.2021x; 1.2021x over previous
#include <cuda_runtime.h>
#include <cstdint>

#define D_MODEL 1024
#define N_HEADS 16
#define D_HEAD  64
#define D_FF    4096
#define BATCH   4
#define SEQ     1024
#define M_TOK   (BATCH*SEQ)   // 4096

// ---------------- scratch (allocation-free: device globals) ----------------
__device__ float g_h  [M_TOK*D_MODEL];
__device__ float g_q  [M_TOK*D_MODEL];
__device__ float g_k  [M_TOK*D_MODEL];
__device__ float g_v  [M_TOK*D_MODEL];
__device__ float g_vT [M_TOK*D_MODEL];
__device__ float g_o1 [M_TOK*D_MODEL];
__device__ float g_h2 [M_TOK*D_MODEL];
__device__ float g_ff [M_TOK*D_FF];

// ---------------- helpers ----------------
__device__ __forceinline__ uint32_t f2tf(float f) {
    uint32_t u;
    asm("cvt.rna.tf32.f32 %0, %1;" : "=r"(u) : "f"(f));
    return u;
}

__device__ __forceinline__ void mma_tf32(float* c, uint32_t a0, uint32_t a1, uint32_t a2, uint32_t a3,
                                         uint32_t b0, uint32_t b1) {
    asm volatile(
        "mma.sync.aligned.m16n8k8.row.col.f32.tf32.tf32.f32 "
        "{%0,%1,%2,%3}, {%4,%5,%6,%7}, {%8,%9}, {%0,%1,%2,%3};\n"
        : "+f"(c[0]), "+f"(c[1]), "+f"(c[2]), "+f"(c[3])
        : "r"(a0), "r"(a1), "r"(a2), "r"(a3), "r"(b0), "r"(b1));
}

// ---------------- LayerNorm (unbiased var, /(std+eps)) ----------------
__global__ void ln_kernel(const float* __restrict__ x, const float* __restrict__ g,
                          const float* __restrict__ b, float* __restrict__ out) {
    int row = blockIdx.x;
    int t = threadIdx.x;  // 256 threads, 4 floats each
    const float4* xr = (const float4*)(x + (size_t)row * D_MODEL);
    float4 v = xr[t];
    __shared__ float red[8];

    float s = v.x + v.y + v.z + v.w;
    #pragma unroll
    for (int o = 16; o; o >>= 1) s += __shfl_xor_sync(0xffffffffu, s, o);
    if ((t & 31) == 0) red[t >> 5] = s;
    __syncthreads();
    float tot = red[0]+red[1]+red[2]+red[3]+red[4]+red[5]+red[6]+red[7];
    float mean = tot * (1.0f / D_MODEL);

    float dx = v.x - mean, dy = v.y - mean, dz = v.z - mean, dw = v.w - mean;
    float ss = dx*dx + dy*dy + dz*dz + dw*dw;
    #pragma unroll
    for (int o = 16; o; o >>= 1) ss += __shfl_xor_sync(0xffffffffu, ss, o);
    __syncthreads();
    if ((t & 31) == 0) red[t >> 5] = ss;
    __syncthreads();
    float vtot = red[0]+red[1]+red[2]+red[3]+red[4]+red[5]+red[6]+red[7];
    float inv = 1.0f / (sqrtf(vtot * (1.0f / (D_MODEL - 1))) + 1e-12f);

    float4 g4 = ((const float4*)g)[t];
    float4 b4 = ((const float4*)b)[t];
    float4 o4;
    o4.x = g4.x * dx * inv + b4.x;
    o4.y = g4.y * dy * inv + b4.y;
    o4.z = g4.z * dz * inv + b4.z;
    o4.w = g4.w * dw * inv + b4.w;
    ((float4*)(out + (size_t)row * D_MODEL))[t] = o4;
}

// ---------------- softmax (in-place over rows of length SEQ) ----------------
__global__ void softmax_kernel(float* __restrict__ attn) {
    size_t row = blockIdx.x;
    float4* p = (float4*)(attn + row * SEQ);
    int t = threadIdx.x;
    float4 v = p[t];
    __shared__ float red[8];

    float mx = fmaxf(fmaxf(v.x, v.y), fmaxf(v.z, v.w));
    #pragma unroll
    for (int o = 16; o; o >>= 1) mx = fmaxf(mx, __shfl_xor_sync(0xffffffffu, mx, o));
    if ((t & 31) == 0) red[t >> 5] = mx;
    __syncthreads();
    mx = fmaxf(fmaxf(fmaxf(red[0],red[1]),fmaxf(red[2],red[3])),
               fmaxf(fmaxf(red[4],red[5]),fmaxf(red[6],red[7])));

    v.x = expf(v.x - mx); v.y = expf(v.y - mx);
    v.z = expf(v.z - mx); v.w = expf(v.w - mx);
    float s = v.x + v.y + v.z + v.w;
    #pragma unroll
    for (int o = 16; o; o >>= 1) s += __shfl_xor_sync(0xffffffffu, s, o);
    __syncthreads();
    if ((t & 31) == 0) red[t >> 5] = s;
    __syncthreads();
    float tot = red[0]+red[1]+red[2]+red[3]+red[4]+red[5]+red[6]+red[7];
    float inv = 1.0f / tot;
    v.x *= inv; v.y *= inv; v.z *= inv; v.w *= inv;
    p[t] = v;
}

// ---------------- V transpose: v[b,s,h,d] -> vT[(b*H+h)*64+d][s] ----------------
__global__ void transpose_v(const float* __restrict__ v, float* __restrict__ vT) {
    __shared__ float tile[32][33];
    int bh = blockIdx.z;             // b*H + h
    int b = bh / N_HEADS, h = bh % N_HEADS;
    int s0 = blockIdx.x * 32;
    int d0 = blockIdx.y * 32;
    int tx = threadIdx.x, ty = threadIdx.y;  // 32 x 8
    const float* src = v + ((size_t)b * SEQ) * D_MODEL + h * D_HEAD;
    #pragma unroll
    for (int i = 0; i < 32; i += 8)
        tile[ty + i][tx] = src[(size_t)(s0 + ty + i) * D_MODEL + d0 + tx];
    __syncthreads();
    float* dst = vT + ((size_t)bh * D_HEAD) * SEQ;
    #pragma unroll
    for (int i = 0; i < 32; i += 8)
        dst[(size_t)(d0 + ty + i) * SEQ + s0 + tx] = tile[tx][ty + i];
}

// ---------------- generalized tf32 GEMM: C = scale*(A[M,K] @ B[N,K]^T) (+bias)(+res)(relu)
// Template config:
//   BM x BN CTA tile, 256 threads = 8 warps arranged WARPS_M x WARPS_N,
//   warp tile = (MT*16) x (NT*8).  Requires WARPS_M*WARPS_N == 8,
//   WARPS_M*MT*16 == BM, WARPS_N*NT*8 == BN, BM,BN multiples of 64.
// Smem: KS=20-word padded rows (proven conflict-free for the mma lane pattern).
#define BK 16
#define KS 20   // padded smem row stride (words)

template<int BM, int BN, int MT, int NT, int WARPS_M>
__global__ void __launch_bounds__(256)
gemm_tf32(const float* __restrict__ A, const float* __restrict__ B,
          float* __restrict__ C, const float* __restrict__ bias,
          const float* __restrict__ res,
          int M, int N, int K, int lda, int ldb, int ldc,
          float scale, int relu, int zmod,
          long long aLo, long long aHi, long long bLo, long long bHi,
          long long cLo, long long cHi)
{
    int z = blockIdx.z;
    int zlo = z % zmod, zhi = z / zmod;
    A += (size_t)zlo * aLo + (size_t)zhi * aHi;
    B += (size_t)zlo * bLo + (size_t)zhi * bHi;
    size_t coff = (size_t)zlo * cLo + (size_t)zhi * cHi;
    C += coff;
    if (res) res += coff;

    __shared__ uint32_t As[2][BM * KS];
    __shared__ uint32_t Bs[2][BN * KS];

    int tid = threadIdx.x;
    int lane = tid & 31;
    int warp = tid >> 5;
    int wm = (warp % WARPS_M) * (MT * 16);
    int wn = (warp / WARPS_M) * (NT * 8);

    int m0 = blockIdx.y * BM;
    int n0 = blockIdx.x * BN;

    int lr = tid >> 2;          // 0..63
    int lc = (tid & 3) * 4;     // 0,4,8,12

    float acc[MT][NT][4];
    #pragma unroll
    for (int i = 0; i < MT; i++)
        #pragma unroll
        for (int j = 0; j < NT; j++)
            #pragma unroll
            for (int c = 0; c < 4; c++) acc[i][j][c] = 0.f;

    float4 aReg[BM / 64], bReg[BN / 64];

    auto loadg = [&](int t) {
        int k0 = t * BK;
        #pragma unroll
        for (int i = 0; i < BM / 64; i++) {
            int gm = m0 + lr + i * 64;
            if (gm < M) aReg[i] = *(const float4*)(A + (size_t)gm * lda + k0 + lc);
            else        aReg[i] = make_float4(0.f, 0.f, 0.f, 0.f);
        }
        #pragma unroll
        for (int i = 0; i < BN / 64; i++) {
            int gn = n0 + lr + i * 64;
            if (gn < N) bReg[i] = *(const float4*)(B + (size_t)gn * ldb + k0 + lc);
            else        bReg[i] = make_float4(0.f, 0.f, 0.f, 0.f);
        }
    };
    auto stores = [&](int buf) {
        #pragma unroll
        for (int i = 0; i < BM / 64; i++) {
            int r = lr + i * 64;
            uint4 ua = make_uint4(f2tf(aReg[i].x), f2tf(aReg[i].y), f2tf(aReg[i].z), f2tf(aReg[i].w));
            *(uint4*)&As[buf][r * KS + lc] = ua;
        }
        #pragma unroll
        for (int i = 0; i < BN / 64; i++) {
            int r = lr + i * 64;
            uint4 ub = make_uint4(f2tf(bReg[i].x), f2tf(bReg[i].y), f2tf(bReg[i].z), f2tf(bReg[i].w));
            *(uint4*)&Bs[buf][r * KS + lc] = ub;
        }
    };
    auto compute = [&](int buf) {
        #pragma unroll
        for (int kk = 0; kk < 2; ++kk) {
            uint32_t af[MT][4];
            #pragma unroll
            for (int mt = 0; mt < MT; ++mt) {
                int row = wm + mt * 16 + (lane >> 2);
                int col = kk * 8 + (lane & 3);
                const uint32_t* p = &As[buf][row * KS + col];
                af[mt][0] = p[0];
                af[mt][1] = p[8 * KS];
                af[mt][2] = p[4];
                af[mt][3] = p[8 * KS + 4];
            }
            #pragma unroll
            for (int nt = 0; nt < NT; ++nt) {
                int rowb = wn + nt * 8 + (lane >> 2);
                int col = kk * 8 + (lane & 3);
                const uint32_t* p = &Bs[buf][rowb * KS + col];
                uint32_t b0 = p[0];
                uint32_t b1 = p[4];
                #pragma unroll
                for (int mt = 0; mt < MT; ++mt)
                    mma_tf32(acc[mt][nt], af[mt][0], af[mt][1], af[mt][2], af[mt][3], b0, b1);
            }
        }
    };

    int nk = K / BK;
    loadg(0); stores(0); __syncthreads();
    int buf = 0;
    for (int t = 0; t < nk; ++t) {
        if (t + 1 < nk) loadg(t + 1);
        compute(buf);
        if (t + 1 < nk) { stores(buf ^ 1); __syncthreads(); }
        buf ^= 1;
    }

    // epilogue (float2 vectorized)
    #pragma unroll
    for (int mt = 0; mt < MT; ++mt) {
        #pragma unroll
        for (int nt = 0; nt < NT; ++nt) {
            int rbase = m0 + wm + mt * 16 + (lane >> 2);
            int cbase = n0 + wn + nt * 8 + (lane & 3) * 2;
            #pragma unroll
            for (int h = 0; h < 2; ++h) {
                int rr = rbase + h * 8;
                if (rr < M && cbase + 1 < N) {
                    float v0 = acc[mt][nt][h * 2 + 0] * scale;
                    float v1 = acc[mt][nt][h * 2 + 1] * scale;
                    if (bias) { float2 bb = *(const float2*)(bias + cbase); v0 += bb.x; v1 += bb.y; }
                    if (res)  { float2 r2 = *(const float2*)(res + (size_t)rr * ldc + cbase); v0 += r2.x; v1 += r2.y; }
                    if (relu) { v0 = fmaxf(v0, 0.f); v1 = fmaxf(v1, 0.f); }
                    *(float2*)(C + (size_t)rr * ldc + cbase) = make_float2(v0, v1);
                } else if (rr < M) {
                    #pragma unroll
                    for (int c = 0; c < 2; ++c) {
                        int cc = cbase + c;
                        if (cc < N) {
                            float val = acc[mt][nt][h * 2 + c] * scale;
                            if (bias) val += bias[cc];
                            if (res)  val += res[(size_t)rr * ldc + cc];
                            if (relu) val = fmaxf(val, 0.f);
                            C[(size_t)rr * ldc + cc] = val;
                        }
                    }
                }
            }
        }
    }
}

// Big-tile config: 128x256 CTA tile, warp grid 2x4, warp tile 64x64
#define GEMM_BIG  gemm_tf32<128, 256, 4, 8, 2>
// Narrow config (ctx, N=64): 128x128 CTA tile, warp grid 4x2, warp tile 32x64
#define GEMM_STD  gemm_tf32<128, 128, 2, 8, 4>

// ---------------- launch ----------------
extern "C" void kernel_launch(void* const* d_in, const int* in_sizes, int n_in,
                              void* d_out, int out_size) {
    const float* x     = (const float*)d_in[0];
    const float* ln1_g = (const float*)d_in[1];
    const float* ln1_b = (const float*)d_in[2];
    const float* wq    = (const float*)d_in[3];
    const float* bq    = (const float*)d_in[4];
    const float* wk    = (const float*)d_in[5];
    const float* bk    = (const float*)d_in[6];
    const float* wv    = (const float*)d_in[7];
    const float* bv    = (const float*)d_in[8];
    const float* ln2_g = (const float*)d_in[9];
    const float* ln2_b = (const float*)d_in[10];
    const float* w1    = (const float*)d_in[11];
    const float* b1    = (const float*)d_in[12];
    const float* w2    = (const float*)d_in[13];
    const float* b2    = (const float*)d_in[14];

    float* out  = (float*)d_out;
    float* attn = out + (size_t)BATCH * SEQ * D_MODEL;

    float *h, *q, *k, *v, *vT, *o1, *h2, *ff;
    cudaGetSymbolAddress((void**)&h,  g_h);
    cudaGetSymbolAddress((void**)&q,  g_q);
    cudaGetSymbolAddress((void**)&k,  g_k);
    cudaGetSymbolAddress((void**)&v,  g_v);
    cudaGetSymbolAddress((void**)&vT, g_vT);
    cudaGetSymbolAddress((void**)&o1, g_o1);
    cudaGetSymbolAddress((void**)&h2, g_h2);
    cudaGetSymbolAddress((void**)&ff, g_ff);

    dim3 blk(256);

    // 1) LN1
    ln_kernel<<<M_TOK, 256>>>(x, ln1_g, ln1_b, h);

    // 2) Q, K, V projections: [4096,1024] x [1024,1024]^T
    GEMM_BIG<<<dim3(4, 32, 1), blk>>>(h, wq, q, bq, nullptr,
        M_TOK, D_MODEL, D_MODEL, D_MODEL, D_MODEL, D_MODEL, 1.f, 0, 1, 0,0,0,0,0,0);
    GEMM_BIG<<<dim3(4, 32, 1), blk>>>(h, wk, k, bk, nullptr,
        M_TOK, D_MODEL, D_MODEL, D_MODEL, D_MODEL, D_MODEL, 1.f, 0, 1, 0,0,0,0,0,0);
    GEMM_BIG<<<dim3(4, 32, 1), blk>>>(h, wv, v, bv, nullptr,
        M_TOK, D_MODEL, D_MODEL, D_MODEL, D_MODEL, D_MODEL, 1.f, 0, 1, 0,0,0,0,0,0);

    // 3) V transpose for ctx GEMM (B operand must be [n][k] = [d][s])
    transpose_v<<<dim3(32, 2, BATCH * N_HEADS), dim3(32, 8)>>>(v, vT);

    // 4) scores = q @ k^T / 8, batched over z = h*B + b, written straight to attn output
    GEMM_BIG<<<dim3(4, 8, N_HEADS * BATCH), blk>>>(q, k, attn, nullptr, nullptr,
        SEQ, SEQ, D_HEAD, D_MODEL, D_MODEL, SEQ, 0.125f, 0, BATCH,
        (long long)SEQ * D_MODEL, 64,
        (long long)SEQ * D_MODEL, 64,
        (long long)SEQ * SEQ, (long long)BATCH * SEQ * SEQ);

    // 5) softmax in place (rows of attn)
    softmax_kernel<<<N_HEADS * BATCH * SEQ, 256>>>(attn);

    // 6) ctx = attn @ v  (+ residual x), batched over z = h*B + b  (N=64 -> std tile)
    GEMM_STD<<<dim3(1, 8, N_HEADS * BATCH), blk>>>(attn, vT, o1, nullptr, x,
        SEQ, D_HEAD, SEQ, SEQ, SEQ, D_MODEL, 1.f, 0, BATCH,
        (long long)SEQ * SEQ, (long long)BATCH * SEQ * SEQ,
        (long long)N_HEADS * D_HEAD * SEQ, (long long)D_HEAD * SEQ,
        (long long)SEQ * D_MODEL, 64);

    // 7) LN2
    ln_kernel<<<M_TOK, 256>>>(o1, ln2_g, ln2_b, h2);

    // 8) FFN1: relu(h2 @ w1^T + b1)
    GEMM_BIG<<<dim3(16, 32, 1), blk>>>(h2, w1, ff, b1, nullptr,
        M_TOK, D_FF, D_MODEL, D_MODEL, D_MODEL, D_FF, 1.f, 1, 1, 0,0,0,0,0,0);

    // 9) FFN2: ff @ w2^T + b2 + o1  -> final out
    GEMM_BIG<<<dim3(4, 32, 1), blk>>>(ff, w2, out, b2, o1,
        M_TOK, D_MODEL, D_FF, D_FF, D_FF, D_MODEL, 1.f, 0, 1, 0,0,0,0,0,0);
}

// round 6
// speedup vs baseline: 1.4225x; 1.1834x over previous
#include <cuda_runtime.h>
#include <cstdint>

#define D_MODEL 1024
#define N_HEADS 16
#define D_HEAD  64
#define D_FF    4096
#define BATCH   4
#define SEQ     1024
#define M_TOK   (BATCH*SEQ)   // 4096

// ---------------- scratch (allocation-free: device globals) ----------------
__device__ float g_h   [M_TOK*D_MODEL];
__device__ float g_q   [M_TOK*D_MODEL];
__device__ float g_k   [M_TOK*D_MODEL];
__device__ float g_v   [M_TOK*D_MODEL];
__device__ float g_vT  [M_TOK*D_MODEL];
__device__ float g_o1  [M_TOK*D_MODEL];
__device__ float g_h2  [M_TOK*D_MODEL];
__device__ float g_ff  [M_TOK*D_FF];
__device__ float g_wqkv[3*D_MODEL*D_MODEL];
__device__ float g_w1r [D_FF*D_MODEL];
__device__ float g_w2r [D_MODEL*D_FF];

// ---------------- helpers ----------------
__device__ __forceinline__ uint32_t f2tf(float f) {
    uint32_t u;
    asm("cvt.rna.tf32.f32 %0, %1;" : "=r"(u) : "f"(f));
    return u;
}
__device__ __forceinline__ float f2tf_f(float f) { return __uint_as_float(f2tf(f)); }

__device__ __forceinline__ void mma_tf32(float* c, uint32_t a0, uint32_t a1, uint32_t a2, uint32_t a3,
                                         uint32_t b0, uint32_t b1) {
    asm volatile(
        "mma.sync.aligned.m16n8k8.row.col.f32.tf32.tf32.f32 "
        "{%0,%1,%2,%3}, {%4,%5,%6,%7}, {%8,%9}, {%0,%1,%2,%3};\n"
        : "+f"(c[0]), "+f"(c[1]), "+f"(c[2]), "+f"(c[3])
        : "r"(a0), "r"(a1), "r"(a2), "r"(a3), "r"(b0), "r"(b1));
}

// ---------------- round-to-tf32 copy ----------------
__global__ void round_copy(const float4* __restrict__ src, float4* __restrict__ dst, int n4) {
    int i = blockIdx.x * blockDim.x + threadIdx.x;
    if (i < n4) {
        float4 v = src[i];
        dst[i] = make_float4(f2tf_f(v.x), f2tf_f(v.y), f2tf_f(v.z), f2tf_f(v.w));
    }
}

// ---------------- LayerNorm (unbiased var, /(std+eps)); optional tf32-rounded out ----
__global__ void ln_kernel(const float* __restrict__ x, const float* __restrict__ g,
                          const float* __restrict__ b, float* __restrict__ out, int rnd) {
    int row = blockIdx.x;
    int t = threadIdx.x;  // 256 threads, 4 floats each
    const float4* xr = (const float4*)(x + (size_t)row * D_MODEL);
    float4 v = xr[t];
    __shared__ float red[8];

    float s = v.x + v.y + v.z + v.w;
    #pragma unroll
    for (int o = 16; o; o >>= 1) s += __shfl_xor_sync(0xffffffffu, s, o);
    if ((t & 31) == 0) red[t >> 5] = s;
    __syncthreads();
    float tot = red[0]+red[1]+red[2]+red[3]+red[4]+red[5]+red[6]+red[7];
    float mean = tot * (1.0f / D_MODEL);

    float dx = v.x - mean, dy = v.y - mean, dz = v.z - mean, dw = v.w - mean;
    float ss = dx*dx + dy*dy + dz*dz + dw*dw;
    #pragma unroll
    for (int o = 16; o; o >>= 1) ss += __shfl_xor_sync(0xffffffffu, ss, o);
    __syncthreads();
    if ((t & 31) == 0) red[t >> 5] = ss;
    __syncthreads();
    float vtot = red[0]+red[1]+red[2]+red[3]+red[4]+red[5]+red[6]+red[7];
    float inv = 1.0f / (sqrtf(vtot * (1.0f / (D_MODEL - 1))) + 1e-12f);

    float4 g4 = ((const float4*)g)[t];
    float4 b4 = ((const float4*)b)[t];
    float4 o4;
    o4.x = g4.x * dx * inv + b4.x;
    o4.y = g4.y * dy * inv + b4.y;
    o4.z = g4.z * dz * inv + b4.z;
    o4.w = g4.w * dw * inv + b4.w;
    if (rnd) o4 = make_float4(f2tf_f(o4.x), f2tf_f(o4.y), f2tf_f(o4.z), f2tf_f(o4.w));
    ((float4*)(out + (size_t)row * D_MODEL))[t] = o4;
}

// ---------------- softmax (in-place over rows of length SEQ) ----------------
__global__ void softmax_kernel(float* __restrict__ attn) {
    size_t row = blockIdx.x;
    float4* p = (float4*)(attn + row * SEQ);
    int t = threadIdx.x;
    float4 v = p[t];
    __shared__ float red[8];

    float mx = fmaxf(fmaxf(v.x, v.y), fmaxf(v.z, v.w));
    #pragma unroll
    for (int o = 16; o; o >>= 1) mx = fmaxf(mx, __shfl_xor_sync(0xffffffffu, mx, o));
    if ((t & 31) == 0) red[t >> 5] = mx;
    __syncthreads();
    mx = fmaxf(fmaxf(fmaxf(red[0],red[1]),fmaxf(red[2],red[3])),
               fmaxf(fmaxf(red[4],red[5]),fmaxf(red[6],red[7])));

    v.x = expf(v.x - mx); v.y = expf(v.y - mx);
    v.z = expf(v.z - mx); v.w = expf(v.w - mx);
    float s = v.x + v.y + v.z + v.w;
    #pragma unroll
    for (int o = 16; o; o >>= 1) s += __shfl_xor_sync(0xffffffffu, s, o);
    __syncthreads();
    if ((t & 31) == 0) red[t >> 5] = s;
    __syncthreads();
    float tot = red[0]+red[1]+red[2]+red[3]+red[4]+red[5]+red[6]+red[7];
    float inv = 1.0f / tot;
    v.x *= inv; v.y *= inv; v.z *= inv; v.w *= inv;
    p[t] = v;
}

// ---------------- V transpose: v[b,s,h,d] -> vT[(b*H+h)*64+d][s] (v pre-rounded) ----
__global__ void transpose_v(const float* __restrict__ v, float* __restrict__ vT) {
    __shared__ float tile[32][33];
    int bh = blockIdx.z;             // b*H + h
    int b = bh / N_HEADS, h = bh % N_HEADS;
    int s0 = blockIdx.x * 32;
    int d0 = blockIdx.y * 32;
    int tx = threadIdx.x, ty = threadIdx.y;  // 32 x 8
    const float* src = v + ((size_t)b * SEQ) * D_MODEL + h * D_HEAD;
    #pragma unroll
    for (int i = 0; i < 32; i += 8)
        tile[ty + i][tx] = src[(size_t)(s0 + ty + i) * D_MODEL + d0 + tx];
    __syncthreads();
    float* dst = vT + ((size_t)bh * D_HEAD) * SEQ;
    #pragma unroll
    for (int i = 0; i < 32; i += 8)
        dst[(size_t)(d0 + ty + i) * SEQ + s0 + tx] = tile[tx][ty + i];
}

// ---------------- tf32 mma.sync GEMM, chunk-permuted smem, LDS.128 fragments -------
// C = scale*(A[M,K] @ B[N,K]^T) (+bias)(+res)(relu)(round)
// 128x128 CTA tile, 8 warps in 4x2 grid, 32x64 warp tile, BK=16.
// smem word layout per buffer (4096 words): A rows 0..127 (16 words/row) then B.
// Within a row of 16 k-values: 16B unit u holds logical chunk t = u ^ ((row>>1)&3),
// chunk t = {k=t, t+4, t+8, t+12}. One LDS.128 of unit (lane&3)^sw yields a full
// mma operand set for both kk-steps. Store side: 4 scalar STS, bank-conflict-free.
// If Ck != null: QKV mode, output columns [0,1024)->C, [1024,2048)->Ck, [2048,3072)->Cv.
template<int CVTA, int CVTB, int ROUND_OUT>
__global__ void __launch_bounds__(256, 2)
gemm_mma(const float* __restrict__ A, const float* __restrict__ B,
         float* __restrict__ C, const float* __restrict__ bias, const float* __restrict__ res,
         float* __restrict__ Ck, float* __restrict__ Cv,
         const float* __restrict__ biask, const float* __restrict__ biasv,
         int M, int N, int K, int lda, int ldb, int ldc,
         float scale, int relu, int zmod,
         long long aLo, long long aHi, long long bLo, long long bHi,
         long long cLo, long long cHi)
{
    __shared__ __align__(16) uint32_t sm[8192];   // 2 bufs x (A 2048 + B 2048) words

    int z = blockIdx.z;
    int zlo = z % zmod, zhi = z / zmod;
    A += (size_t)zlo * aLo + (size_t)zhi * aHi;
    B += (size_t)zlo * bLo + (size_t)zhi * bHi;
    size_t coff = (size_t)zlo * cLo + (size_t)zhi * cHi;
    C += coff;
    if (res) res += coff;

    const int tid = threadIdx.x, lane = tid & 31, warp = tid >> 5;
    const int wm = (warp & 3) * 32, wn = (warp >> 2) * 64;
    const int m0 = blockIdx.y * 128, n0 = blockIdx.x * 128;

    // staging-side addressing
    const int lr = tid >> 2, c4 = tid & 3, sw = (lr >> 1) & 3;
    uint32_t stA[4];
    #pragma unroll
    for (int j = 0; j < 4; j++) stA[j] = lr * 16 + 4 * (j ^ sw) + c4;  // buf0 A region
    // compute-side bases (chunk index provably independent of mt/h/nt)
    const int ft = lane & 3, frl = lane >> 2;
    const int fu = ft ^ ((frl >> 1) & 3);
    uint32_t ldA = (uint32_t)((wm + frl) * 16 + 4 * fu);
    uint32_t ldB = (uint32_t)(2048 + (wn + frl) * 16 + 4 * fu);

    float acc[2][8][4];
    #pragma unroll
    for (int i = 0; i < 2; i++)
        #pragma unroll
        for (int j = 0; j < 8; j++)
            #pragma unroll
            for (int c = 0; c < 4; c++) acc[i][j][c] = 0.f;

    float4 aR[2], bR[2];

    auto loadg = [&](int t) {
        int k0 = t * 16 + c4 * 4;
        #pragma unroll
        for (int i = 0; i < 2; i++) {
            int gm = m0 + lr + i * 64;
            aR[i] = (gm < M) ? *(const float4*)(A + (size_t)gm * lda + k0)
                             : make_float4(0.f, 0.f, 0.f, 0.f);
            int gn = n0 + lr + i * 64;
            bR[i] = (gn < N) ? *(const float4*)(B + (size_t)gn * ldb + k0)
                             : make_float4(0.f, 0.f, 0.f, 0.f);
        }
    };
    auto stores = [&]() {
        #pragma unroll
        for (int i = 0; i < 2; i++) {
            float av[4] = {aR[i].x, aR[i].y, aR[i].z, aR[i].w};
            float bv[4] = {bR[i].x, bR[i].y, bR[i].z, bR[i].w};
            #pragma unroll
            for (int j = 0; j < 4; j++) {
                sm[stA[j] + i * 1024]        = CVTA ? f2tf(av[j]) : __float_as_uint(av[j]);
                sm[stA[j] + i * 1024 + 2048] = CVTB ? f2tf(bv[j]) : __float_as_uint(bv[j]);
            }
        }
        #pragma unroll
        for (int j = 0; j < 4; j++) stA[j] ^= 4096;
    };
    auto compute = [&]() {
        uint4 af[2][2];
        #pragma unroll
        for (int mt = 0; mt < 2; mt++)
            #pragma unroll
            for (int h = 0; h < 2; h++)
                af[mt][h] = *(const uint4*)&sm[ldA + mt * 256 + h * 128];
        #pragma unroll
        for (int nt = 0; nt < 8; nt++) {
            uint4 bf = *(const uint4*)&sm[ldB + nt * 128];
            #pragma unroll
            for (int mt = 0; mt < 2; mt++) {
                mma_tf32(acc[mt][nt], af[mt][0].x, af[mt][1].x, af[mt][0].y, af[mt][1].y,
                         bf.x, bf.y);
                mma_tf32(acc[mt][nt], af[mt][0].z, af[mt][1].z, af[mt][0].w, af[mt][1].w,
                         bf.z, bf.w);
            }
        }
        ldA ^= 4096; ldB ^= 4096;
    };

    int nk = K / 16;
    loadg(0); stores(); __syncthreads();
    for (int t = 0; t < nk; ++t) {
        if (t + 1 < nk) loadg(t + 1);
        compute();
        if (t + 1 < nk) stores();
        __syncthreads();
    }

    // epilogue (QKV 3-way select, float2-vectorized)
    float* Cp = C; const float* bp = bias; int noff = 0;
    if (Ck) {
        if (n0 >= 2048)      { Cp = Cv; bp = biasv; noff = 2048; }
        else if (n0 >= 1024) { Cp = Ck; bp = biask; noff = 1024; }
    }
    #pragma unroll
    for (int mt = 0; mt < 2; ++mt) {
        #pragma unroll
        for (int nt = 0; nt < 8; ++nt) {
            int rbase = m0 + wm + mt * 16 + (lane >> 2);
            int cbase = n0 + wn + nt * 8 + (lane & 3) * 2;
            #pragma unroll
            for (int h = 0; h < 2; ++h) {
                int rr = rbase + h * 8;
                int cl = cbase - noff;
                if (rr < M && cbase + 1 < N) {
                    float v0 = acc[mt][nt][h * 2 + 0] * scale;
                    float v1 = acc[mt][nt][h * 2 + 1] * scale;
                    if (bp)  { float2 bb = *(const float2*)(bp + cl); v0 += bb.x; v1 += bb.y; }
                    if (res) { float2 r2 = *(const float2*)(res + (size_t)rr * ldc + cl); v0 += r2.x; v1 += r2.y; }
                    if (relu) { v0 = fmaxf(v0, 0.f); v1 = fmaxf(v1, 0.f); }
                    if (ROUND_OUT) { v0 = f2tf_f(v0); v1 = f2tf_f(v1); }
                    *(float2*)(Cp + (size_t)rr * ldc + cl) = make_float2(v0, v1);
                } else if (rr < M) {
                    #pragma unroll
                    for (int c = 0; c < 2; ++c) {
                        int cc = cbase + c;
                        if (cc < N) {
                            float val = acc[mt][nt][h * 2 + c] * scale;
                            if (bp)  val += bp[cc - noff];
                            if (res) val += res[(size_t)rr * ldc + cc - noff];
                            if (relu) val = fmaxf(val, 0.f);
                            if (ROUND_OUT) val = f2tf_f(val);
                            Cp[(size_t)rr * ldc + cc - noff] = val;
                        }
                    }
                }
            }
        }
    }
}

// ---------------- launch ----------------
extern "C" void kernel_launch(void* const* d_in, const int* in_sizes, int n_in,
                              void* d_out, int out_size) {
    const float* x     = (const float*)d_in[0];
    const float* ln1_g = (const float*)d_in[1];
    const float* ln1_b = (const float*)d_in[2];
    const float* wq    = (const float*)d_in[3];
    const float* bq    = (const float*)d_in[4];
    const float* wk    = (const float*)d_in[5];
    const float* bk    = (const float*)d_in[6];
    const float* wv    = (const float*)d_in[7];
    const float* bv    = (const float*)d_in[8];
    const float* ln2_g = (const float*)d_in[9];
    const float* ln2_b = (const float*)d_in[10];
    const float* w1    = (const float*)d_in[11];
    const float* b1    = (const float*)d_in[12];
    const float* w2    = (const float*)d_in[13];
    const float* b2    = (const float*)d_in[14];

    float* out  = (float*)d_out;
    float* attn = out + (size_t)BATCH * SEQ * D_MODEL;

    float *h, *q, *k, *v, *vT, *o1, *h2, *ff, *wqkv, *w1r, *w2r;
    cudaGetSymbolAddress((void**)&h,    g_h);
    cudaGetSymbolAddress((void**)&q,    g_q);
    cudaGetSymbolAddress((void**)&k,    g_k);
    cudaGetSymbolAddress((void**)&v,    g_v);
    cudaGetSymbolAddress((void**)&vT,   g_vT);
    cudaGetSymbolAddress((void**)&o1,   g_o1);
    cudaGetSymbolAddress((void**)&h2,   g_h2);
    cudaGetSymbolAddress((void**)&ff,   g_ff);
    cudaGetSymbolAddress((void**)&wqkv, g_wqkv);
    cudaGetSymbolAddress((void**)&w1r,  g_w1r);
    cudaGetSymbolAddress((void**)&w2r,  g_w2r);

    dim3 blk(256);
    const int N4_1M = D_MODEL * D_MODEL / 4;      // 262144
    const int N4_4M = D_FF * D_MODEL / 4;         // 1048576

    // 0) pre-round weights into scratch (tf32 rounding hoisted out of GEMMs)
    round_copy<<<(N4_1M + 255) / 256, 256>>>((const float4*)wq, (float4*)(wqkv), N4_1M);
    round_copy<<<(N4_1M + 255) / 256, 256>>>((const float4*)wk, (float4*)(wqkv + D_MODEL * D_MODEL), N4_1M);
    round_copy<<<(N4_1M + 255) / 256, 256>>>((const float4*)wv, (float4*)(wqkv + 2 * D_MODEL * D_MODEL), N4_1M);
    round_copy<<<(N4_4M + 255) / 256, 256>>>((const float4*)w1, (float4*)w1r, N4_4M);
    round_copy<<<(N4_4M + 255) / 256, 256>>>((const float4*)w2, (float4*)w2r, N4_4M);

    // 1) LN1 (rounded output)
    ln_kernel<<<M_TOK, 256>>>(x, ln1_g, ln1_b, h, 1);

    // 2) fused QKV: [4096,3072] = h @ wqkv^T, outputs split to q/k/v, rounded
    gemm_mma<0, 0, 1><<<dim3(24, 32, 1), blk>>>(h, wqkv, q, bq, nullptr, k, v, bk, bv,
        M_TOK, 3 * D_MODEL, D_MODEL, D_MODEL, D_MODEL, D_MODEL, 1.f, 0, 1, 0,0,0,0,0,0);

    // 3) V transpose (v already rounded)
    transpose_v<<<dim3(32, 2, BATCH * N_HEADS), dim3(32, 8)>>>(v, vT);

    // 4) scores = q @ k^T / 8, z = h*B + b, straight into attn output (exact fp32)
    gemm_mma<0, 0, 0><<<dim3(8, 8, N_HEADS * BATCH), blk>>>(q, k, attn, nullptr, nullptr,
        nullptr, nullptr, nullptr, nullptr,
        SEQ, SEQ, D_HEAD, D_MODEL, D_MODEL, SEQ, 0.125f, 0, BATCH,
        (long long)SEQ * D_MODEL, 64,
        (long long)SEQ * D_MODEL, 64,
        (long long)SEQ * SEQ, (long long)BATCH * SEQ * SEQ);

    // 5) softmax in place
    softmax_kernel<<<N_HEADS * BATCH * SEQ, 256>>>(attn);

    // 6) ctx = attn @ vT^T (+ residual x); A needs in-loop cvt (attn is exact)
    gemm_mma<1, 0, 0><<<dim3(1, 8, N_HEADS * BATCH), blk>>>(attn, vT, o1, nullptr, x,
        nullptr, nullptr, nullptr, nullptr,
        SEQ, D_HEAD, SEQ, SEQ, SEQ, D_MODEL, 1.f, 0, BATCH,
        (long long)SEQ * SEQ, (long long)BATCH * SEQ * SEQ,
        (long long)N_HEADS * D_HEAD * SEQ, (long long)D_HEAD * SEQ,
        (long long)SEQ * D_MODEL, 64);

    // 7) LN2 (rounded output)
    ln_kernel<<<M_TOK, 256>>>(o1, ln2_g, ln2_b, h2, 1);

    // 8) FFN1: relu(h2 @ w1^T + b1), rounded output
    gemm_mma<0, 0, 1><<<dim3(32, 32, 1), blk>>>(h2, w1r, ff, b1, nullptr,
        nullptr, nullptr, nullptr, nullptr,
        M_TOK, D_FF, D_MODEL, D_MODEL, D_MODEL, D_FF, 1.f, 1, 1, 0,0,0,0,0,0);

    // 9) FFN2: ff @ w2^T + b2 + o1 -> final out (exact)
    gemm_mma<0, 0, 0><<<dim3(8, 32, 1), blk>>>(ff, w2r, out, b2, o1,
        nullptr, nullptr, nullptr, nullptr,
        M_TOK, D_MODEL, D_FF, D_FF, D_FF, D_MODEL, 1.f, 0, 1, 0,0,0,0,0,0);
}